// round 11
// baseline (speedup 1.0000x reference)
#include <cuda_runtime.h>

// gabor_fixedResponse, round 11: de-fused two-kernel structure.
//   Kernel 1 (maxfft): per-filter CTA. Heavy (f<64): top-32-Q packed Horner
//     DFT. Light (f>=64): top-2-Q micro-DFT. Writes g_L[f] = ln(1/maxfft).
//     No output stores -> short (~4us).
//   Kernel 2 (out): CTA = (f, 32 rows). inv known at start -> zero barriers
//     after smem init; each warp streams 2 rows (zero STG.128 for dead
//     128-elem blocks, expf+carrier for live ones). Pure LSU/BW-bound.

#define NFILT  512
#define NBINS  8
#define WHALF  3
#define DEADX  9.6f
#define FSPLIT 64

typedef unsigned long long ull;

__device__ float g_L[NFILT];   // ln(1/maxfft) per filter

__device__ __forceinline__ ull pk2(float lo, float hi) {
    ull r; asm("mov.b64 %0, {%1,%2};" : "=l"(r) : "f"(lo), "f"(hi)); return r;
}
__device__ __forceinline__ void upk2(ull v, float& lo, float& hi) {
    asm("mov.b64 {%0,%1}, %2;" : "=f"(lo), "=f"(hi) : "l"(v));
}
__device__ __forceinline__ ull fma2(ull a, ull b, ull c) {
    ull d; asm("fma.rn.f32x2 %0, %1, %2, %3;" : "=l"(d) : "l"(a), "l"(b), "l"(c)); return d;
}
__device__ __forceinline__ ull mul2(ull a, ull b) {
    ull d; asm("mul.rn.f32x2 %0, %1, %2;" : "=l"(d) : "l"(a), "l"(b)); return d;
}

constexpr double W0D  = 6.283185307179586 / 16000.0;
constexpr float  C32F = (float)W0D;
constexpr float  DCFF = (float)((double)C32F - W0D);
#define PI1024 3.0679615757712823e-3f   /* pi/1024 */
#define PI256  1.2271846303085129e-2f   /* pi/256  */

__device__ __forceinline__ int live_v0_t(float thr, int h) {
    int v0 = (int)ceilf(((float)(897 - 512 * h) - thr) * (1.0f / 128.0f));
    return v0 < 0 ? 0 : (v0 > 4 ? 4 : v0);
}

// ---------------- Kernel 1: maxfft -> g_L[f] ----------------
__global__ __launch_bounds__(512, 3)
void maxfft_kernel(const float* __restrict__ Q, const float* __restrict__ fc) {
    int f    = blockIdx.x;
    int tid  = threadIdx.x;
    int lane = tid & 31;
    int w    = tid >> 5;

    __shared__ float s_carr[1024];
    __shared__ float s_bq[64];
    __shared__ int   s_sel[32];
    __shared__ int   s_top[2];
    __shared__ float s_ar[4][4][32][3];
    __shared__ float s_ai[4][4][32][3];
    __shared__ float s_part[16];

    float fcv = __ldg(&fc[f]);
    float wph = C32F * fcv;
    float e1  = fmaf(C32F, fcv, -wph);
    float dwf = fmaf(fcv, DCFF, -e1);
    int stepm = 2 * f + 1;

    // carrier row: exact int phase reduction + tiny fp32 delta
    {
        float2 cv;
        int t0 = tid << 1;
#pragma unroll
        for (int e = 0; e < 2; e++) {
            int n = t0 + e + 1;
            int m = (stepm * n) & 2047;
            float nf  = (float)n;
            float p   = wph * nf;
            float eta = fmaf(wph, nf, -p);
            float del = fmaf(dwf, nf, eta);
            ((float*)&cv)[e] = __cosf(fmaf(PI1024, (float)m, del));
        }
        *(float2*)(s_carr + t0) = cv;
    }
    if (tid < 64) {
        float qv = Q[tid * NFILT + f];
        s_bq[tid] = (fcv / qv) * 1.2533141373155003f / 16000.0f;
    }

    int klo = ((2 * f + 3) >> 2) - WHALF;
    if (klo < 0) klo = 0;
    if (klo > 256 - (NBINS - 1)) klo = 256 - (NBINS - 1);

    __syncthreads();

    if (f < FSPLIT) {
        // ===== HEAVY: top-32-Q full packed Horner DFT =====
        if (tid < 64) {
            float myb = s_bq[tid];
            int rank = 0;
#pragma unroll 8
            for (int j = 0; j < 64; j++) {
                float o = s_bq[j];
                rank += (o < myb) || (o == myb && j < tid);
            }
            if (rank < 32) s_sel[rank] = tid;
        }
        __syncthreads();

        int seg = w >> 2;
        int bqg = w & 3;
        int kb  = klo + 2 * bqg;
        int b   = s_sel[lane];
        float bq = s_bq[b];
        float t2 = bq * bq;

        float c0, s0, c1, s1, cq0, sq0, cq1, sq1;
        float th0 = (float)kb       * (3.14159265358979f / 256.0f);
        float th1 = (float)(kb + 1) * (3.14159265358979f / 256.0f);
        __sincosf(th0, &s0, &c0);  __sincosf(th1, &s1, &c1);
        __sincosf(2.0f * th0, &sq0, &cq0);  __sincosf(2.0f * th1, &sq1, &cq1);
        ull uc2  = pk2(c0, c1),   us2 = pk2(s0, s1);
        ull ucq  = pk2(cq0, cq1), usq = pk2(sq0, sq1), nusq = pk2(-sq0, -sq1);
        ull ar2 = 0ull, ai2 = 0ull;

        int   n0 = seg * 128 + 1;
        float x0 = bq * (float)n0;
        float g  = __expf(-x0 * x0);
        float r  = __expf(-t2 * (float)(2 * n0 + 1));
        float qq = __expf(-2.0f * t2);

        const float4* cp4 = (const float4*)(s_carr + seg * 128);
#pragma unroll 2
        for (int j = 0; j < 32; j++) {
            if (!__ballot_sync(0xffffffffu, g > 1e-10f)) break;
            float4 c = cp4[j];
            float y0 = g * c.x; g *= r; r *= qq;
            float y1 = g * c.y; g *= r; r *= qq;
            ull yy0 = pk2(y0, y0), yy1 = pk2(y1, y1);
            {
                ull s1v = mul2(yy0, us2);
                ull s2v = fma2(ar2, usq, s1v);
                ull ain = fma2(ai2, ucq, s2v);
                ull s3v = fma2(yy0, uc2, yy1);
                ull s4v = fma2(ai2, nusq, s3v);
                ar2 = fma2(ar2, ucq, s4v);
                ai2 = ain;
            }
            y0 = g * c.z; g *= r; r *= qq;
            y1 = g * c.w; g *= r; r *= qq;
            yy0 = pk2(y0, y0); yy1 = pk2(y1, y1);
            {
                ull s1v = mul2(yy0, us2);
                ull s2v = fma2(ar2, usq, s1v);
                ull ain = fma2(ai2, ucq, s2v);
                ull s3v = fma2(yy0, uc2, yy1);
                ull s4v = fma2(ai2, nusq, s3v);
                ar2 = fma2(ar2, ucq, s4v);
                ai2 = ain;
            }
        }
        upk2(ar2, s_ar[seg][bqg][lane][0], s_ar[seg][bqg][lane][1]);
        upk2(ai2, s_ai[seg][bqg][lane][0], s_ai[seg][bqg][lane][1]);
        __syncthreads();

        if (tid < 32) {
            int bb = tid;
            float msq = 0.0f;
#pragma unroll
            for (int i = 0; i < NBINS; i++) {
                int k = klo + i;
                int h = i >> 1, ii = i & 1;
                float R = 0.0f, I = 0.0f;
#pragma unroll
                for (int s = 0; s < 4; s++) {
                    float rr2 = s_ar[s][h][bb][ii];
                    float iv  = s_ai[s][h][bb][ii];
                    int mc = (k * (3 - s)) & 3;
                    float r2 = (mc == 0) ? rr2 : (mc == 1) ? -iv : (mc == 2) ? -rr2 : iv;
                    float i2 = (mc == 0) ? iv  : (mc == 1) ?  rr2 : (mc == 2) ? -iv : -rr2;
                    R += r2; I += i2;
                }
                msq = fmaxf(msq, fmaf(R, R, I * I));
            }
#pragma unroll
            for (int o = 16; o; o >>= 1)
                msq = fmaxf(msq, __shfl_xor_sync(0xffffffffu, msq, o));
            if (lane == 0) g_L[f] = __logf(rsqrtf(msq));
        }
    } else {
        // ===== LIGHT: top-2-Q micro-DFT =====
        if (w == 0) {
            float qA = Q[lane * NFILT + f];
            float qB = Q[(lane + 32) * NFILT + f];
            float v1, v2; int i1, i2;
            if (qA >= qB) { v1 = qA; i1 = lane;      v2 = qB; i2 = lane + 32; }
            else          { v1 = qB; i1 = lane + 32; v2 = qA; i2 = lane; }
#pragma unroll
            for (int o = 16; o; o >>= 1) {
                float u1 = __shfl_xor_sync(0xffffffffu, v1, o);
                int   j1 = __shfl_xor_sync(0xffffffffu, i1, o);
                float u2 = __shfl_xor_sync(0xffffffffu, v2, o);
                int   j2 = __shfl_xor_sync(0xffffffffu, i2, o);
                if (u1 > v1) {
                    if (v1 >= u2) { v2 = v1; i2 = i1; } else { v2 = u2; i2 = j2; }
                    v1 = u1; i1 = j1;
                } else if (u1 > v2) { v2 = u1; i2 = j1; }
            }
            if (lane == 0) { s_top[0] = i1; s_top[1] = i2; }
        }
        __syncthreads();

        int wb = w >> 3;
        int k  = klo + (w & 7);
        int bsel = s_top[wb];
        float bqL = s_bq[bsel];
        float t2L = bqL * bqL;

        int   ns = lane + 1;
        float x0 = bqL * (float)ns;
        float g  = __expf(-x0 * x0);
        float rr = __expf(-t2L * (float)(64 * ns + 1024));
        float q32 = __expf(-2048.0f * t2L);

        int m0 = (k * ns) & 511;
        int ms = (k << 5) & 511;
        float cr, ci, sc, ss;
        __sincosf((float)m0 * PI256, &ci, &cr);
        __sincosf((float)ms * PI256, &ss, &sc);

        float R = 0.0f, I = 0.0f;
#pragma unroll 4
        for (int t = 0; t < 16; t++) {
            float y = g * s_carr[lane + (t << 5)];
            R = fmaf(y, cr, R);
            I = fmaf(y, ci, I);
            float ncr = fmaf(cr, sc, -(ci * ss));
            ci = fmaf(ci, sc, cr * ss);
            cr = ncr;
            g *= rr; rr *= q32;
        }
#pragma unroll
        for (int o = 16; o; o >>= 1) {
            R += __shfl_xor_sync(0xffffffffu, R, o);
            I += __shfl_xor_sync(0xffffffffu, I, o);
        }
        if (lane == 0) s_part[w] = fmaf(R, R, I * I);
        __syncthreads();
        if (tid == 0) {
            float m = s_part[0];
#pragma unroll
            for (int i = 1; i < 16; i++) m = fmaxf(m, s_part[i]);
            g_L[f] = __logf(rsqrtf(m));
        }
    }
}

// ---------------- Kernel 2: barrier-free output stream ----------------
// CTA = (f, half hh of 32 rows). Warp streams 2 rows; per row: zero STG.128
// for dead 128-elem blocks, expf * carrier for live ones. No inter-warp deps.
__global__ __launch_bounds__(512, 4)
void out_kernel(const float* __restrict__ Q, const float* __restrict__ fc,
                float* __restrict__ out) {
    int bid  = blockIdx.x;
    int f    = bid >> 1;
    int hh   = bid & 1;
    int tid  = threadIdx.x;
    int lane = tid & 31;
    int w    = tid >> 5;

    __shared__ float s_carr[1024];
    __shared__ float s_bq[32];
    __shared__ float s_thr[32];

    float fcv = __ldg(&fc[f]);
    float wph = C32F * fcv;
    float e1  = fmaf(C32F, fcv, -wph);
    float dwf = fmaf(fcv, DCFF, -e1);
    int stepm = 2 * f + 1;

    {
        float2 cv;
        int t0 = tid << 1;
#pragma unroll
        for (int e = 0; e < 2; e++) {
            int n = t0 + e + 1;
            int m = (stepm * n) & 2047;
            float nf  = (float)n;
            float p   = wph * nf;
            float eta = fmaf(wph, nf, -p);
            float del = fmaf(dwf, nf, eta);
            ((float*)&cv)[e] = __cosf(fmaf(PI1024, (float)m, del));
        }
        *(float2*)(s_carr + t0) = cv;
    }
    if (tid < 32) {
        float qv = Q[(hh * 32 + tid) * NFILT + f];
        float bq = (fcv / qv) * 1.2533141373155003f / 16000.0f;
        s_bq[tid]  = bq;
        s_thr[tid] = DEADX / bq;
    }
    float L = g_L[f];
    __syncthreads();                 // the only barrier

    const float4 z4 = make_float4(0.f, 0.f, 0.f, 0.f);

#pragma unroll
    for (int jl = 0; jl < 2; jl++) {
        int rloc  = (w << 1) | jl;
        float bqr = s_bq[rloc];
        float thr = s_thr[rloc];
        int grow  = hh * 32 + rloc;
        float* rowp = out + (((size_t)(grow * NFILT + f)) << 10) + (lane << 2);
#pragma unroll
        for (int h = 0; h < 2; h++) {
            int v0 = live_v0_t(thr, h);
            float* p = rowp + (h << 9);
            for (int v = 0; v < v0; v++) { __stcs((float4*)p, z4); p += 128; }
            if (v0 < 4) {
                int nl0 = 1024 - (h << 9) - (v0 << 7) - (lane << 2);  // n at e=0
                float nf = (float)nl0;
                const float4* cp = (const float4*)(s_carr + (nl0 - 4));
                for (int v = v0; v < 4; v++) {
                    float4 c = *cp;
                    float x0v = bqr * nf;
                    float x1v = bqr * (nf - 1.0f);
                    float x2v = bqr * (nf - 2.0f);
                    float x3v = bqr * (nf - 3.0f);
                    float4 o;
                    o.x = __expf(fmaf(-x0v, x0v, L)) * c.w;   // n = nl
                    o.y = __expf(fmaf(-x1v, x1v, L)) * c.z;
                    o.z = __expf(fmaf(-x2v, x2v, L)) * c.y;
                    o.w = __expf(fmaf(-x3v, x3v, L)) * c.x;   // n = nl-3
                    __stcs((float4*)p, o);
                    p  += 128;
                    cp -= 32;
                    nf -= 128.0f;
                }
            }
        }
    }
}

extern "C" void kernel_launch(void* const* d_in, const int* in_sizes, int n_in,
                              void* d_out, int out_size) {
    const float* Q  = (const float*)d_in[0];
    const float* fc = (const float*)d_in[1];
    float* out = (float*)d_out;
    (void)in_sizes; (void)n_in; (void)out_size;

    maxfft_kernel<<<NFILT, 512>>>(Q, fc);
    out_kernel<<<2 * NFILT, 512>>>(Q, fc, out);
}

// round 13
// speedup vs baseline: 1.1153x; 1.1153x over previous
#include <cuda_runtime.h>
#include <cstdint>

// gabor_fixedResponse, round 13 (= round 12 resubmit; prior run died at CUDA
// init with cudaErrorSystemNotReady BEFORE any checkpoint -> infra flake).
//   Fused kernel + async bulk zero stores:
//   ~70% of outputs are exact zeros (envelope underflow, contiguous prefix of
//   each 512-elem half-row). Lane 0 issues ONE cp.async.bulk per dead prefix
//   from a constant 2KB zero smem page, BEFORE the DFT -> the async write
//   stream overlaps the fma-bound DFT and skips per-warp STG.128 issue cost.
//   Live blocks keep the STG path. DFT: f<64 top-32-Q packed Horner;
//   f>=64 top-2-Q micro-DFT (both validated in earlier rounds).

#define NFILT  512
#define NBINS  8
#define WHALF  3
#define DEADX  9.6f
#define FSPLIT 64

typedef unsigned long long ull;

__device__ __forceinline__ ull pk2(float lo, float hi) {
    ull r; asm("mov.b64 %0, {%1,%2};" : "=l"(r) : "f"(lo), "f"(hi)); return r;
}
__device__ __forceinline__ void upk2(ull v, float& lo, float& hi) {
    asm("mov.b64 {%0,%1}, %2;" : "=f"(lo), "=f"(hi) : "l"(v));
}
__device__ __forceinline__ ull fma2(ull a, ull b, ull c) {
    ull d; asm("fma.rn.f32x2 %0, %1, %2, %3;" : "=l"(d) : "l"(a), "l"(b), "l"(c)); return d;
}
__device__ __forceinline__ ull mul2(ull a, ull b) {
    ull d; asm("mul.rn.f32x2 %0, %1, %2;" : "=l"(d) : "l"(a), "l"(b)); return d;
}
__device__ __forceinline__ void bulk_zero(float* gdst, uint32_t ssrc, uint32_t bytes) {
    asm volatile("cp.async.bulk.global.shared::cta.bulk_group [%0], [%1], %2;"
                 :: "l"(gdst), "r"(ssrc), "r"(bytes) : "memory");
}

constexpr double W0D  = 6.283185307179586 / 16000.0;
constexpr float  C32F = (float)W0D;
constexpr float  DCFF = (float)((double)C32F - W0D);
#define PI1024 3.0679615757712823e-3f   /* pi/1024 */
#define PI256  1.2271846303085129e-2f   /* pi/256  */

__device__ __forceinline__ int live_v0_t(float thr, int h) {
    int v0 = (int)ceilf(((float)(897 - 512 * h) - thr) * (1.0f / 128.0f));
    return v0 < 0 ? 0 : (v0 > 4 ? 4 : v0);
}

__global__ __launch_bounds__(512, 3)
void fused_kernel(const float* __restrict__ Q, const float* __restrict__ fc,
                  float* __restrict__ out) {
    int f    = blockIdx.x;
    int tid  = threadIdx.x;
    int lane = tid & 31;
    int w    = tid >> 5;

    __shared__ float s_carr[1024];
    __shared__ __align__(16) float s_zero[512];    // 2KB constant zero page
    __shared__ float s_bq[64];
    __shared__ float s_thr[64];
    __shared__ int   s_sel[32];
    __shared__ int   s_top[2];
    __shared__ float s_ar[4][4][32][3];
    __shared__ float s_ai[4][4][32][3];
    __shared__ float s_max[2];
    __shared__ float s_part[16];

    float fcv = __ldg(&fc[f]);
    float wph = C32F * fcv;
    float e1  = fmaf(C32F, fcv, -wph);
    float dwf = fmaf(fcv, DCFF, -e1);              // fl(w) - pi*(2f+1)/1024
    int stepm = 2 * f + 1;

    // carrier row: exact int phase reduction + tiny fp32 delta
    {
        float2 cv;
        int t0 = tid << 1;
#pragma unroll
        for (int e = 0; e < 2; e++) {
            int n = t0 + e + 1;
            int m = (stepm * n) & 2047;
            float nf  = (float)n;
            float p   = wph * nf;
            float eta = fmaf(wph, nf, -p);
            float del = fmaf(dwf, nf, eta);
            ((float*)&cv)[e] = __cosf(fmaf(PI1024, (float)m, del));
        }
        *(float2*)(s_carr + t0) = cv;
    }
    s_zero[tid] = 0.0f;
    if (tid < 64) {
        float qv = Q[tid * NFILT + f];
        float bq = (fcv / qv) * 1.2533141373155003f / 16000.0f;
        s_bq[tid]  = bq;
        s_thr[tid] = DEADX / bq;
    }

    int klo = ((2 * f + 3) >> 2) - WHALF;
    if (klo < 0) klo = 0;
    if (klo > 256 - (NBINS - 1)) klo = 256 - (NBINS - 1);

    __syncthreads();                               // carrier/zero/bq/thr ready
    asm volatile("fence.proxy.async.shared::cta;" ::: "memory");

    // ---- Pass A: async bulk zero stores for dead prefixes (lane 0 only) ----
    if (lane == 0) {
        uint32_t zaddr = (uint32_t)__cvta_generic_to_shared(s_zero);
        float* rowp = out + (((size_t)(w << 2) * NFILT + f) << 10);
#pragma unroll
        for (int rloc = 0; rloc < 4; rloc++) {
            float thr = s_thr[(w << 2) + rloc];
#pragma unroll
            for (int h = 0; h < 2; h++) {
                int v0 = live_v0_t(thr, h);
                if (v0 > 0)
                    bulk_zero(rowp + (h << 9), zaddr, (uint32_t)(v0 << 9));
            }
            rowp += (size_t)NFILT << 10;
        }
    }
    asm volatile("cp.async.bulk.commit_group;" ::: "memory");

    if (f < FSPLIT) {
        // ========== HEAVY: top-32-Q (smallest-bq) packed Horner DFT ==========
        if (tid < 64) {
            float myb = s_bq[tid];
            int rank = 0;
#pragma unroll 8
            for (int j = 0; j < 64; j++) {
                float o = s_bq[j];
                rank += (o < myb) || (o == myb && j < tid);
            }
            if (rank < 32) s_sel[rank] = tid;
        }
        __syncthreads();                            // s_sel ready

        int seg = w >> 2;            // 0..3, 128 samples
        int bqg = w & 3;             // bin pair 0..3
        int kb  = klo + 2 * bqg;
        int b   = s_sel[lane];
        float bq = s_bq[b];
        float t2 = bq * bq;

        float c0, s0, c1, s1, cq0, sq0, cq1, sq1;
        float th0 = (float)kb       * (3.14159265358979f / 256.0f);
        float th1 = (float)(kb + 1) * (3.14159265358979f / 256.0f);
        __sincosf(th0, &s0, &c0);  __sincosf(th1, &s1, &c1);
        __sincosf(2.0f * th0, &sq0, &cq0);  __sincosf(2.0f * th1, &sq1, &cq1);
        ull uc2  = pk2(c0, c1),   us2 = pk2(s0, s1);
        ull ucq  = pk2(cq0, cq1), usq = pk2(sq0, sq1), nusq = pk2(-sq0, -sq1);
        ull ar2 = 0ull, ai2 = 0ull;

        int   n0 = seg * 128 + 1;
        float x0 = bq * (float)n0;
        float g  = __expf(-x0 * x0);
        float r  = __expf(-t2 * (float)(2 * n0 + 1));
        float qq = __expf(-2.0f * t2);

        const float4* cp4 = (const float4*)(s_carr + seg * 128);
#pragma unroll 2
        for (int j = 0; j < 32; j++) {
            if (!__ballot_sync(0xffffffffu, g > 1e-10f)) break;
            float4 c = cp4[j];
            float y0 = g * c.x; g *= r; r *= qq;
            float y1 = g * c.y; g *= r; r *= qq;
            ull yy0 = pk2(y0, y0), yy1 = pk2(y1, y1);
            {
                ull s1v = mul2(yy0, us2);
                ull s2v = fma2(ar2, usq, s1v);
                ull ain = fma2(ai2, ucq, s2v);
                ull s3v = fma2(yy0, uc2, yy1);
                ull s4v = fma2(ai2, nusq, s3v);
                ar2 = fma2(ar2, ucq, s4v);
                ai2 = ain;
            }
            y0 = g * c.z; g *= r; r *= qq;
            y1 = g * c.w; g *= r; r *= qq;
            yy0 = pk2(y0, y0); yy1 = pk2(y1, y1);
            {
                ull s1v = mul2(yy0, us2);
                ull s2v = fma2(ar2, usq, s1v);
                ull ain = fma2(ai2, ucq, s2v);
                ull s3v = fma2(yy0, uc2, yy1);
                ull s4v = fma2(ai2, nusq, s3v);
                ar2 = fma2(ar2, ucq, s4v);
                ai2 = ain;
            }
        }
        upk2(ar2, s_ar[seg][bqg][lane][0], s_ar[seg][bqg][lane][1]);
        upk2(ai2, s_ai[seg][bqg][lane][0], s_ai[seg][bqg][lane][1]);
        __syncthreads();

        // combine segs (u^128 = i^k exactly) + max over 32 ranks
        if (tid < 32) {
            int bb = tid;
            float msq = 0.0f;
#pragma unroll
            for (int i = 0; i < NBINS; i++) {
                int k = klo + i;
                int h = i >> 1, ii = i & 1;
                float R = 0.0f, I = 0.0f;
#pragma unroll
                for (int s = 0; s < 4; s++) {
                    float rr2 = s_ar[s][h][bb][ii];
                    float iv  = s_ai[s][h][bb][ii];
                    int mc = (k * (3 - s)) & 3;
                    float r2 = (mc == 0) ? rr2 : (mc == 1) ? -iv : (mc == 2) ? -rr2 : iv;
                    float i2 = (mc == 0) ? iv  : (mc == 1) ?  rr2 : (mc == 2) ? -iv : -rr2;
                    R += r2; I += i2;
                }
                msq = fmaxf(msq, fmaf(R, R, I * I));
            }
#pragma unroll
            for (int o = 16; o; o >>= 1)
                msq = fmaxf(msq, __shfl_xor_sync(0xffffffffu, msq, o));
            if (lane == 0) { s_max[0] = msq; s_max[1] = msq; }
        }
        __syncthreads();
    } else {
        // ========== LIGHT: top-2-Q micro-DFT ==========
        if (w == 0) {
            float qA = Q[lane * NFILT + f];
            float qB = Q[(lane + 32) * NFILT + f];
            float v1, v2; int i1, i2;
            if (qA >= qB) { v1 = qA; i1 = lane;      v2 = qB; i2 = lane + 32; }
            else          { v1 = qB; i1 = lane + 32; v2 = qA; i2 = lane; }
#pragma unroll
            for (int o = 16; o; o >>= 1) {
                float u1 = __shfl_xor_sync(0xffffffffu, v1, o);
                int   j1 = __shfl_xor_sync(0xffffffffu, i1, o);
                float u2 = __shfl_xor_sync(0xffffffffu, v2, o);
                int   j2 = __shfl_xor_sync(0xffffffffu, i2, o);
                if (u1 > v1) {
                    if (v1 >= u2) { v2 = v1; i2 = i1; } else { v2 = u2; i2 = j2; }
                    v1 = u1; i1 = j1;
                } else if (u1 > v2) { v2 = u1; i2 = j1; }
            }
            if (lane == 0) { s_top[0] = i1; s_top[1] = i2; }
        }
        __syncthreads();                            // s_top ready

        int wb = w >> 3;
        int k  = klo + (w & 7);
        int bsel = s_top[wb];
        float bqL = s_bq[bsel];
        float t2L = bqL * bqL;

        int   ns = lane + 1;
        float x0 = bqL * (float)ns;
        float g  = __expf(-x0 * x0);
        float rr = __expf(-t2L * (float)(64 * ns + 1024));
        float q32 = __expf(-2048.0f * t2L);

        int m0 = (k * ns) & 511;
        int ms = (k << 5) & 511;
        float cr, ci, sc, ss;
        __sincosf((float)m0 * PI256, &ci, &cr);
        __sincosf((float)ms * PI256, &ss, &sc);

        float R = 0.0f, I = 0.0f;
#pragma unroll 4
        for (int t = 0; t < 16; t++) {
            float y = g * s_carr[lane + (t << 5)];
            R = fmaf(y, cr, R);
            I = fmaf(y, ci, I);
            float ncr = fmaf(cr, sc, -(ci * ss));
            ci = fmaf(ci, sc, cr * ss);
            cr = ncr;
            g *= rr; rr *= q32;
        }
#pragma unroll
        for (int o = 16; o; o >>= 1) {
            R += __shfl_xor_sync(0xffffffffu, R, o);
            I += __shfl_xor_sync(0xffffffffu, I, o);
        }
        if (lane == 0) s_part[w] = fmaf(R, R, I * I);
        __syncthreads();
        if (tid == 0) {
            float m = s_part[0];
#pragma unroll
            for (int i = 1; i < 16; i++) m = fmaxf(m, s_part[i]);
            s_max[0] = m; s_max[1] = m;
        }
        __syncthreads();
    }

    float inv = rsqrtf(fmaxf(s_max[0], s_max[1]));
    float L   = __logf(inv);      // fold 1/maxfft into the exp argument

    // ---------------- Pass B: live blocks only (STG path) ----------------
    {
        float* rowp = out + (((size_t)(w << 2) * NFILT + f) << 10) + (lane << 2);
#pragma unroll
        for (int rloc = 0; rloc < 4; rloc++) {
            int   rr  = (w << 2) + rloc;
            float bqr = s_bq[rr];
            float thr = s_thr[rr];
#pragma unroll
            for (int h = 0; h < 2; h++) {
                int v0 = live_v0_t(thr, h);
                if (v0 < 4) {
                    int nl0 = 1024 - (h << 9) - (v0 << 7) - (lane << 2);  // n at e=0
                    float nf = (float)nl0;
                    const float4* cp = (const float4*)(s_carr + (nl0 - 4));
                    float* p = rowp + (h << 9) + (v0 << 7);
                    for (int v = v0; v < 4; v++) {
                        float4 c = *cp;
                        float x0v = bqr * nf;
                        float x1v = bqr * (nf - 1.0f);
                        float x2v = bqr * (nf - 2.0f);
                        float x3v = bqr * (nf - 3.0f);
                        float4 o;
                        o.x = __expf(fmaf(-x0v, x0v, L)) * c.w;   // n = nl
                        o.y = __expf(fmaf(-x1v, x1v, L)) * c.z;
                        o.z = __expf(fmaf(-x2v, x2v, L)) * c.y;
                        o.w = __expf(fmaf(-x3v, x3v, L)) * c.x;   // n = nl-3
                        __stcs((float4*)p, o);
                        p  += 128;
                        cp -= 32;
                        nf -= 128.0f;
                    }
                }
            }
            rowp += (size_t)NFILT << 10;
        }
    }

    // drain the bulk zero-store group before CTA exit (smem source must stay
    // valid until the copies complete)
    asm volatile("cp.async.bulk.wait_group 0;" ::: "memory");
}

extern "C" void kernel_launch(void* const* d_in, const int* in_sizes, int n_in,
                              void* d_out, int out_size) {
    const float* Q  = (const float*)d_in[0];
    const float* fc = (const float*)d_in[1];
    float* out = (float*)d_out;
    (void)in_sizes; (void)n_in; (void)out_size;

    fused_kernel<<<NFILT, 512>>>(Q, fc, out);
}

// round 16
// speedup vs baseline: 1.2009x; 1.0768x over previous
#include <cuda_runtime.h>
#include <cstdint>

// gabor_fixedResponse, round 14: R13 + MUFU-free Pass B.
//   Theory: the invisible binder is the MUFU/xu pipe (ncu summary never shows
//   it): ~10M per-element __expf in Pass B. Replace with chained geometric
//   recurrences: per (row,half) 3 expf seeds + per-row 3 constants, then
//   2 FMUL per element. v iterated descending (n ascending, env decreasing)
//   so all chain ratios < 1 -> underflow to 0 is benign & matches reference.
//   Everything else identical to R13 (bulk zero stores, top-32/top-2 DFT).

#define NFILT  512
#define NBINS  8
#define WHALF  3
#define DEADX  9.6f
#define FSPLIT 64

typedef unsigned long long ull;

__device__ __forceinline__ ull pk2(float lo, float hi) {
    ull r; asm("mov.b64 %0, {%1,%2};" : "=l"(r) : "f"(lo), "f"(hi)); return r;
}
__device__ __forceinline__ void upk2(ull v, float& lo, float& hi) {
    asm("mov.b64 {%0,%1}, %2;" : "=f"(lo), "=f"(hi) : "l"(v));
}
__device__ __forceinline__ ull fma2(ull a, ull b, ull c) {
    ull d; asm("fma.rn.f32x2 %0, %1, %2, %3;" : "=l"(d) : "l"(a), "l"(b), "l"(c)); return d;
}
__device__ __forceinline__ ull mul2(ull a, ull b) {
    ull d; asm("mul.rn.f32x2 %0, %1, %2;" : "=l"(d) : "l"(a), "l"(b)); return d;
}
__device__ __forceinline__ void bulk_zero(float* gdst, uint32_t ssrc, uint32_t bytes) {
    asm volatile("cp.async.bulk.global.shared::cta.bulk_group [%0], [%1], %2;"
                 :: "l"(gdst), "r"(ssrc), "r"(bytes) : "memory");
}

constexpr double W0D  = 6.283185307179586 / 16000.0;
constexpr float  C32F = (float)W0D;
constexpr float  DCFF = (float)((double)C32F - W0D);
#define PI1024 3.0679615757712823e-3f   /* pi/1024 */
#define PI256  1.2271846303085129e-2f   /* pi/256  */

__device__ __forceinline__ int live_v0_t(float thr, int h) {
    int v0 = (int)ceilf(((float)(897 - 512 * h) - thr) * (1.0f / 128.0f));
    return v0 < 0 ? 0 : (v0 > 4 ? 4 : v0);
}

__global__ __launch_bounds__(512, 3)
void fused_kernel(const float* __restrict__ Q, const float* __restrict__ fc,
                  float* __restrict__ out) {
    int f    = blockIdx.x;
    int tid  = threadIdx.x;
    int lane = tid & 31;
    int w    = tid >> 5;

    __shared__ float s_carr[1024];
    __shared__ __align__(16) float s_zero[512];    // 2KB constant zero page
    __shared__ float s_bq[64];
    __shared__ float s_thr[64];
    __shared__ int   s_sel[32];
    __shared__ int   s_top[2];
    __shared__ float s_ar[4][4][32][3];
    __shared__ float s_ai[4][4][32][3];
    __shared__ float s_max[2];
    __shared__ float s_part[16];

    float fcv = __ldg(&fc[f]);
    float wph = C32F * fcv;
    float e1  = fmaf(C32F, fcv, -wph);
    float dwf = fmaf(fcv, DCFF, -e1);              // fl(w) - pi*(2f+1)/1024
    int stepm = 2 * f + 1;

    // carrier row: exact int phase reduction + tiny fp32 delta
    {
        float2 cv;
        int t0 = tid << 1;
#pragma unroll
        for (int e = 0; e < 2; e++) {
            int n = t0 + e + 1;
            int m = (stepm * n) & 2047;
            float nf  = (float)n;
            float p   = wph * nf;
            float eta = fmaf(wph, nf, -p);
            float del = fmaf(dwf, nf, eta);
            ((float*)&cv)[e] = __cosf(fmaf(PI1024, (float)m, del));
        }
        *(float2*)(s_carr + t0) = cv;
    }
    s_zero[tid] = 0.0f;
    if (tid < 64) {
        float qv = Q[tid * NFILT + f];
        float bq = (fcv / qv) * 1.2533141373155003f / 16000.0f;
        s_bq[tid]  = bq;
        s_thr[tid] = DEADX / bq;
    }

    int klo = ((2 * f + 3) >> 2) - WHALF;
    if (klo < 0) klo = 0;
    if (klo > 256 - (NBINS - 1)) klo = 256 - (NBINS - 1);

    __syncthreads();                               // carrier/zero/bq/thr ready
    asm volatile("fence.proxy.async.shared::cta;" ::: "memory");

    // ---- Pass A: async bulk zero stores for dead prefixes (lane 0 only) ----
    if (lane == 0) {
        uint32_t zaddr = (uint32_t)__cvta_generic_to_shared(s_zero);
        float* rowp = out + (((size_t)(w << 2) * NFILT + f) << 10);
#pragma unroll
        for (int rloc = 0; rloc < 4; rloc++) {
            float thr = s_thr[(w << 2) + rloc];
#pragma unroll
            for (int h = 0; h < 2; h++) {
                int v0 = live_v0_t(thr, h);
                if (v0 > 0)
                    bulk_zero(rowp + (h << 9), zaddr, (uint32_t)(v0 << 9));
            }
            rowp += (size_t)NFILT << 10;
        }
    }
    asm volatile("cp.async.bulk.commit_group;" ::: "memory");

    if (f < FSPLIT) {
        // ========== HEAVY: top-32-Q (smallest-bq) packed Horner DFT ==========
        if (tid < 64) {
            float myb = s_bq[tid];
            int rank = 0;
#pragma unroll 8
            for (int j = 0; j < 64; j++) {
                float o = s_bq[j];
                rank += (o < myb) || (o == myb && j < tid);
            }
            if (rank < 32) s_sel[rank] = tid;
        }
        __syncthreads();                            // s_sel ready

        int seg = w >> 2;            // 0..3, 128 samples
        int bqg = w & 3;             // bin pair 0..3
        int kb  = klo + 2 * bqg;
        int b   = s_sel[lane];
        float bq = s_bq[b];
        float t2 = bq * bq;

        float c0, s0, c1, s1, cq0, sq0, cq1, sq1;
        float th0 = (float)kb       * (3.14159265358979f / 256.0f);
        float th1 = (float)(kb + 1) * (3.14159265358979f / 256.0f);
        __sincosf(th0, &s0, &c0);  __sincosf(th1, &s1, &c1);
        __sincosf(2.0f * th0, &sq0, &cq0);  __sincosf(2.0f * th1, &sq1, &cq1);
        ull uc2  = pk2(c0, c1),   us2 = pk2(s0, s1);
        ull ucq  = pk2(cq0, cq1), usq = pk2(sq0, sq1), nusq = pk2(-sq0, -sq1);
        ull ar2 = 0ull, ai2 = 0ull;

        int   n0 = seg * 128 + 1;
        float x0 = bq * (float)n0;
        float g  = __expf(-x0 * x0);
        float r  = __expf(-t2 * (float)(2 * n0 + 1));
        float qq = __expf(-2.0f * t2);

        const float4* cp4 = (const float4*)(s_carr + seg * 128);
#pragma unroll 2
        for (int j = 0; j < 32; j++) {
            if (!__ballot_sync(0xffffffffu, g > 1e-10f)) break;
            float4 c = cp4[j];
            float y0 = g * c.x; g *= r; r *= qq;
            float y1 = g * c.y; g *= r; r *= qq;
            ull yy0 = pk2(y0, y0), yy1 = pk2(y1, y1);
            {
                ull s1v = mul2(yy0, us2);
                ull s2v = fma2(ar2, usq, s1v);
                ull ain = fma2(ai2, ucq, s2v);
                ull s3v = fma2(yy0, uc2, yy1);
                ull s4v = fma2(ai2, nusq, s3v);
                ar2 = fma2(ar2, ucq, s4v);
                ai2 = ain;
            }
            y0 = g * c.z; g *= r; r *= qq;
            y1 = g * c.w; g *= r; r *= qq;
            yy0 = pk2(y0, y0); yy1 = pk2(y1, y1);
            {
                ull s1v = mul2(yy0, us2);
                ull s2v = fma2(ar2, usq, s1v);
                ull ain = fma2(ai2, ucq, s2v);
                ull s3v = fma2(yy0, uc2, yy1);
                ull s4v = fma2(ai2, nusq, s3v);
                ar2 = fma2(ar2, ucq, s4v);
                ai2 = ain;
            }
        }
        upk2(ar2, s_ar[seg][bqg][lane][0], s_ar[seg][bqg][lane][1]);
        upk2(ai2, s_ai[seg][bqg][lane][0], s_ai[seg][bqg][lane][1]);
        __syncthreads();

        // combine segs (u^128 = i^k exactly) + max over 32 ranks
        if (tid < 32) {
            int bb = tid;
            float msq = 0.0f;
#pragma unroll
            for (int i = 0; i < NBINS; i++) {
                int k = klo + i;
                int h = i >> 1, ii = i & 1;
                float R = 0.0f, I = 0.0f;
#pragma unroll
                for (int s = 0; s < 4; s++) {
                    float rr2 = s_ar[s][h][bb][ii];
                    float iv  = s_ai[s][h][bb][ii];
                    int mc = (k * (3 - s)) & 3;
                    float r2 = (mc == 0) ? rr2 : (mc == 1) ? -iv : (mc == 2) ? -rr2 : iv;
                    float i2 = (mc == 0) ? iv  : (mc == 1) ?  rr2 : (mc == 2) ? -iv : -rr2;
                    R += r2; I += i2;
                }
                msq = fmaxf(msq, fmaf(R, R, I * I));
            }
#pragma unroll
            for (int o = 16; o; o >>= 1)
                msq = fmaxf(msq, __shfl_xor_sync(0xffffffffu, msq, o));
            if (lane == 0) { s_max[0] = msq; s_max[1] = msq; }
        }
        __syncthreads();
    } else {
        // ========== LIGHT: top-2-Q micro-DFT ==========
        if (w == 0) {
            float qA = Q[lane * NFILT + f];
            float qB = Q[(lane + 32) * NFILT + f];
            float v1, v2; int i1, i2;
            if (qA >= qB) { v1 = qA; i1 = lane;      v2 = qB; i2 = lane + 32; }
            else          { v1 = qB; i1 = lane + 32; v2 = qA; i2 = lane; }
#pragma unroll
            for (int o = 16; o; o >>= 1) {
                float u1 = __shfl_xor_sync(0xffffffffu, v1, o);
                int   j1 = __shfl_xor_sync(0xffffffffu, i1, o);
                float u2 = __shfl_xor_sync(0xffffffffu, v2, o);
                int   j2 = __shfl_xor_sync(0xffffffffu, i2, o);
                if (u1 > v1) {
                    if (v1 >= u2) { v2 = v1; i2 = i1; } else { v2 = u2; i2 = j2; }
                    v1 = u1; i1 = j1;
                } else if (u1 > v2) { v2 = u1; i2 = j1; }
            }
            if (lane == 0) { s_top[0] = i1; s_top[1] = i2; }
        }
        __syncthreads();                            // s_top ready

        int wb = w >> 3;
        int k  = klo + (w & 7);
        int bsel = s_top[wb];
        float bqL = s_bq[bsel];
        float t2L = bqL * bqL;

        int   ns = lane + 1;
        float x0 = bqL * (float)ns;
        float g  = __expf(-x0 * x0);
        float rr = __expf(-t2L * (float)(64 * ns + 1024));
        float q32 = __expf(-2048.0f * t2L);

        int m0 = (k * ns) & 511;
        int ms = (k << 5) & 511;
        float cr, ci, sc, ss;
        __sincosf((float)m0 * PI256, &ci, &cr);
        __sincosf((float)ms * PI256, &ss, &sc);

        float R = 0.0f, I = 0.0f;
#pragma unroll 4
        for (int t = 0; t < 16; t++) {
            float y = g * s_carr[lane + (t << 5)];
            R = fmaf(y, cr, R);
            I = fmaf(y, ci, I);
            float ncr = fmaf(cr, sc, -(ci * ss));
            ci = fmaf(ci, sc, cr * ss);
            cr = ncr;
            g *= rr; rr *= q32;
        }
#pragma unroll
        for (int o = 16; o; o >>= 1) {
            R += __shfl_xor_sync(0xffffffffu, R, o);
            I += __shfl_xor_sync(0xffffffffu, I, o);
        }
        if (lane == 0) s_part[w] = fmaf(R, R, I * I);
        __syncthreads();
        if (tid == 0) {
            float m = s_part[0];
#pragma unroll
            for (int i = 1; i < 16; i++) m = fmaxf(m, s_part[i]);
            s_max[0] = m; s_max[1] = m;
        }
        __syncthreads();
    }

    float inv = rsqrtf(fmaxf(s_max[0], s_max[1]));
    float L   = __logf(inv);      // fold 1/maxfft into the exp argument

    // -------- Pass B: live blocks, MUFU-free chained recurrences --------
    // v descending 3..v0 (n ascending, env decreasing, all ratios < 1).
    // Per (row,half): 3 expf seeds; per row: 3 expf constants; then 2 FMUL/elem.
    {
        float* rowp = out + (((size_t)(w << 2) * NFILT + f) << 10) + (lane << 2);
#pragma unroll
        for (int rloc = 0; rloc < 4; rloc++) {
            int   rr  = (w << 2) + rloc;
            float bqr = s_bq[rr];
            float thr = s_thr[rr];
            float t2  = bqr * bqr;
            float qq  = __expf(-2.0f * t2);        // e-step ratio-of-ratio
            float qe  = __expf(-256.0f * t2);      // re across v-steps
            float qv  = __expf(-32768.0f * t2);    // rv across v-steps
#pragma unroll
            for (int h = 0; h < 2; h++) {
                int v0 = live_v0_t(thr, h);
                if (v0 < 4) {
                    int n3 = 1024 - (h << 9) - 384 - (lane << 2) - 3; // min n @ v=3
                    float nf  = (float)n3;
                    float x   = bqr * nf;
                    float env = __expf(fmaf(-x, x, L));               // env(n3)*inv
                    float reb = __expf(-t2 * (2.0f * nf + 1.0f));     // env(n+1)/env(n) @ n3
                    float rv  = __expf(-t2 * (256.0f * nf + 16384.0f)); // env(n+128)/env(n) @ n3
                    const float4* cp = (const float4*)(s_carr + (n3 - 1));
                    float* p = rowp + (h << 9) + (3 << 7);
                    for (int v = 3; v >= v0; v--) {
                        float4 c = *cp;
                        float re = reb;
                        float4 o;
                        o.w = env * c.x;                 // n = n3   (t-slot e=3)
                        float ee1 = env * re;  re *= qq;
                        o.z = ee1 * c.y;                 // n = n3+1
                        float ee2 = ee1 * re;  re *= qq;
                        o.y = ee2 * c.z;                 // n = n3+2
                        float ee3 = ee2 * re;
                        o.x = ee3 * c.w;                 // n = n3+3 = nl
                        __stcs((float4*)p, o);
                        p  -= 128;
                        cp += 32;
                        env *= rv;  rv *= qv;  reb *= qe;
                    }
                }
            }
            rowp += (size_t)NFILT << 10;
        }
    }

    // drain the bulk zero-store group before CTA exit
    asm volatile("cp.async.bulk.wait_group 0;" ::: "memory");
}

extern "C" void kernel_launch(void* const* d_in, const int* in_sizes, int n_in,
                              void* d_out, int out_size) {
    const float* Q  = (const float*)d_in[0];
    const float* fc = (const float*)d_in[1];
    float* out = (float*)d_out;
    (void)in_sizes; (void)n_in; (void)out_size;

    fused_kernel<<<NFILT, 512>>>(Q, fc, out);
}